// round 1
// baseline (speedup 1.0000x reference)
#include <cuda_runtime.h>
#include <cstdint>

#define N_NODES 50000
#define N_EDGES 800000
#define D_IN 128
#define H_DIM 128
#define D_OUT 64

// ---------------- device scratch (static, no allocation) ----------------
__device__ float g_agg[N_NODES * D_IN];   // 25.6 MB aggregation buffer (reused both layers)
__device__ float g_t1[N_NODES * H_DIM];   // 25.6 MB layer-1 activations
__device__ int   g_deg[N_NODES];
__device__ int   g_off[N_NODES + 1];
__device__ int   g_cursor[N_NODES];
__device__ int   g_csr[N_EDGES];
__device__ int   g_is64;

// ---------------- dtype detection: int64 vs int32 edge_index ----------------
// If edge_index is int64 (little-endian, values < 2^31), every odd int32 word
// of the first 64 pairs is the zero high-word. If int32, those are random
// node ids (all-zero probability ~ (2e-5)^64 ~ 0).
__global__ void k_detect(const int* __restrict__ ei32) {
    if (threadIdx.x == 0 && blockIdx.x == 0) {
        int orv = 0;
#pragma unroll
        for (int i = 0; i < 64; i++) orv |= ei32[2 * i + 1];
        g_is64 = (orv == 0) ? 1 : 0;
    }
}

__global__ void k_zero_deg() {
    int i = blockIdx.x * blockDim.x + threadIdx.x;
    if (i < N_NODES) g_deg[i] = 0;
}

__global__ void k_hist(const void* __restrict__ ei) {
    int e = blockIdx.x * blockDim.x + threadIdx.x;
    if (e >= N_EDGES) return;
    int dst = g_is64 ? (int)((const long long*)ei)[N_EDGES + e]
                     : ((const int*)ei)[N_EDGES + e];
    atomicAdd(&g_deg[dst], 1);
}

// single-block exclusive scan of g_deg -> g_off (+ copy to g_cursor)
__global__ void k_scan() {
    __shared__ int sums[1024];
    const int t = threadIdx.x;
    const int C = (N_NODES + 1023) / 1024;   // 49
    int start = t * C;
    int end = min(start + C, N_NODES);
    int s = 0;
    for (int i = start; i < end; i++) s += g_deg[i];
    sums[t] = s;
    __syncthreads();
    for (int off = 1; off < 1024; off <<= 1) {
        int add = (t >= off) ? sums[t - off] : 0;
        __syncthreads();
        sums[t] += add;
        __syncthreads();
    }
    int run = (t == 0) ? 0 : sums[t - 1];
    for (int i = start; i < end; i++) {
        g_off[i] = run;
        g_cursor[i] = run;
        run += g_deg[i];
    }
    if (t == 1023) g_off[N_NODES] = run;   // = N_EDGES
}

__global__ void k_scatter(const void* __restrict__ ei) {
    int e = blockIdx.x * blockDim.x + threadIdx.x;
    if (e >= N_EDGES) return;
    int src, dst;
    if (g_is64) {
        src = (int)((const long long*)ei)[e];
        dst = (int)((const long long*)ei)[N_EDGES + e];
    } else {
        src = ((const int*)ei)[e];
        dst = ((const int*)ei)[N_EDGES + e];
    }
    int pos = atomicAdd(&g_cursor[dst], 1);
    g_csr[pos] = src;
}

// ---------------- gather-based aggregation: warp per node, float4 lanes ----------------
__global__ void k_agg(const float* __restrict__ in, float* __restrict__ out) {
    int gw = (blockIdx.x * blockDim.x + threadIdx.x) >> 5;
    int lane = threadIdx.x & 31;
    if (gw >= N_NODES) return;
    int beg = g_off[gw], end = g_off[gw + 1];
    const float4* base = (const float4*)in;
    float4 acc = make_float4(0.f, 0.f, 0.f, 0.f);
    int j = beg;
    for (; j + 4 <= end; j += 4) {   // MLP=4 independent row gathers
        int s0 = g_csr[j], s1 = g_csr[j + 1], s2 = g_csr[j + 2], s3 = g_csr[j + 3];
        float4 a = base[s0 * 32 + lane];
        float4 b = base[s1 * 32 + lane];
        float4 c = base[s2 * 32 + lane];
        float4 d = base[s3 * 32 + lane];
        acc.x += (a.x + b.x) + (c.x + d.x);
        acc.y += (a.y + b.y) + (c.y + d.y);
        acc.z += (a.z + b.z) + (c.z + d.z);
        acc.w += (a.w + b.w) + (c.w + d.w);
    }
    for (; j < end; j++) {
        float4 a = base[g_csr[j] * 32 + lane];
        acc.x += a.x; acc.y += a.y; acc.z += a.z; acc.w += a.w;
    }
    ((float4*)out)[gw * 32 + lane] = acc;
}

// ---------------- fused dual-GEMM: out[n][h] = act(Acat[n][:] . Wcat[h][:] + b[h]) ----------------
// Acat = [agg_row | x_row] (K=256), Wcat = [Wrel_row | Wroot_row].
// Persistent blocks, weights loaded to smem once. Padded stride 65 float4
// (=260 floats) -> conflict-free LDS.128 in every 8-lane phase.
template <int HOUT, bool RELU>
__global__ void __launch_bounds__(256, 1)
k_gemm(const float* __restrict__ A, const float* __restrict__ X,
       const float4* __restrict__ Wrel4, const float4* __restrict__ Wroot4,
       const float* __restrict__ bias, float* __restrict__ out) {
    extern __shared__ float4 sm4[];
    float4* Wc = sm4;                  // [HOUT][65]
    float4* As = sm4 + HOUT * 65;      // [64][65]
    const int tid = threadIdx.x;

    // load concatenated weights once
    for (int idx = tid; idx < HOUT * 32; idx += 256) {
        int h = idx >> 5, kq = idx & 31;
        Wc[h * 65 + kq]      = Wrel4[h * 32 + kq];
        Wc[h * 65 + 32 + kq] = Wroot4[h * 32 + kq];
    }
    __syncthreads();

    const int tx = tid & 15, ty = tid >> 4;
    constexpr int JH = HOUT / 16;
    const int NT = (N_NODES + 63) >> 6;

    for (int tile = blockIdx.x; tile < NT; tile += gridDim.x) {
        const int n0 = tile << 6;
        // stage A tile: 64 nodes x 64 float4 (agg | x)
        for (int idx = tid; idx < 64 * 64; idx += 256) {
            int r = idx >> 6, kq = idx & 63;
            int n = n0 + r;
            float4 v = make_float4(0.f, 0.f, 0.f, 0.f);
            if (n < N_NODES)
                v = (kq < 32) ? ((const float4*)A)[n * 32 + kq]
                              : ((const float4*)X)[n * 32 + kq - 32];
            As[r * 65 + kq] = v;
        }
        __syncthreads();

        float acc[4][JH];
#pragma unroll
        for (int i = 0; i < 4; i++)
#pragma unroll
            for (int j = 0; j < JH; j++) acc[i][j] = 0.f;

        const float4* Ar0 = As + (ty * 4) * 65;
#pragma unroll 4
        for (int kq = 0; kq < 64; kq++) {
            float4 a0 = Ar0[kq];
            float4 a1 = Ar0[65 + kq];
            float4 a2 = Ar0[130 + kq];
            float4 a3 = Ar0[195 + kq];
#pragma unroll
            for (int j = 0; j < JH; j++) {
                float4 w = Wc[(tx + j * 16) * 65 + kq];
                acc[0][j] += a0.x * w.x + a0.y * w.y + a0.z * w.z + a0.w * w.w;
                acc[1][j] += a1.x * w.x + a1.y * w.y + a1.z * w.z + a1.w * w.w;
                acc[2][j] += a2.x * w.x + a2.y * w.y + a2.z * w.z + a2.w * w.w;
                acc[3][j] += a3.x * w.x + a3.y * w.y + a3.z * w.z + a3.w * w.w;
            }
        }

#pragma unroll
        for (int i = 0; i < 4; i++) {
            int n = n0 + ty * 4 + i;
            if (n < N_NODES) {
#pragma unroll
                for (int j = 0; j < JH; j++) {
                    int h = tx + j * 16;
                    float v = acc[i][j] + __ldg(&bias[h]);
                    if (RELU) v = fmaxf(v, 0.f);
                    out[n * HOUT + h] = v;
                }
            }
        }
        __syncthreads();
    }
}

// ---------------- launch ----------------
extern "C" void kernel_launch(void* const* d_in, const int* in_sizes, int n_in,
                              void* d_out, int out_size) {
    const float* x      = (const float*)d_in[0];
    const void*  ei     = d_in[1];
    const float* Wrel1  = (const float*)d_in[2];
    const float* Wroot1 = (const float*)d_in[3];
    const float* b1     = (const float*)d_in[4];
    const float* Wrel2  = (const float*)d_in[5];
    const float* Wroot2 = (const float*)d_in[6];
    const float* b2     = (const float*)d_in[7];
    float* out = (float*)d_out;

    void *p_agg = nullptr, *p_t1 = nullptr;
    cudaGetSymbolAddress(&p_agg, g_agg);
    cudaGetSymbolAddress(&p_t1, g_t1);

    const int SM1 = (H_DIM + 64) * 65 * (int)sizeof(float4);   // 199,680 B
    const int SM2 = (D_OUT + 64) * 65 * (int)sizeof(float4);   // 133,120 B
    cudaFuncSetAttribute(k_gemm<H_DIM, true>,
                         cudaFuncAttributeMaxDynamicSharedMemorySize, SM1);
    cudaFuncSetAttribute(k_gemm<D_OUT, false>,
                         cudaFuncAttributeMaxDynamicSharedMemorySize, SM2);

    // CSR build (per call; deterministic work, graph-capturable)
    k_detect<<<1, 32>>>((const int*)ei);
    k_zero_deg<<<(N_NODES + 255) / 256, 256>>>();
    k_hist<<<(N_EDGES + 255) / 256, 256>>>(ei);
    k_scan<<<1, 1024>>>();
    k_scatter<<<(N_EDGES + 255) / 256, 256>>>(ei);

    // layer 1
    k_agg<<<(N_NODES * 32 + 255) / 256, 256>>>(x, (float*)p_agg);
    k_gemm<H_DIM, true><<<148, 256, SM1>>>((const float*)p_agg, x,
                                           (const float4*)Wrel1, (const float4*)Wroot1,
                                           b1, (float*)p_t1);
    // layer 2
    k_agg<<<(N_NODES * 32 + 255) / 256, 256>>>((const float*)p_t1, (float*)p_agg);
    k_gemm<D_OUT, false><<<148, 256, SM2>>>((const float*)p_agg, (const float*)p_t1,
                                            (const float4*)Wrel2, (const float4*)Wroot2,
                                            b2, out);
}

// round 2
// speedup vs baseline: 1.6118x; 1.6118x over previous
#include <cuda_runtime.h>
#include <cstdint>

#define N_NODES 50000
#define N_EDGES 800000
#define D_IN 128
#define H_DIM 128
#define D_OUT 64

#define SCAN_BLK 256
#define NBLK ((N_NODES + SCAN_BLK - 1) / SCAN_BLK)   // 196

typedef unsigned long long ull;

// ---------------- device scratch (static, no allocation) ----------------
__device__ float g_vs1[N_NODES * 256];   // layer1 GEMM out: [v(128) | s(128)] per node
__device__ float g_t1 [N_NODES * 128];   // layer1 activations
__device__ float g_vs2[N_NODES * 128];   // layer2 GEMM out: [u(64) | r(64)] per node
__device__ int   g_deg[N_NODES];
__device__ int   g_off[N_NODES + 1];
__device__ int   g_cursor[N_NODES];
__device__ int   g_csr[N_EDGES];
__device__ int   g_bsum[NBLK];
__device__ int   g_is64;

// ---------------- int64 vs int32 edge_index detection ----------------
__global__ void k_detect(const int* __restrict__ ei32) {
    if (threadIdx.x == 0 && blockIdx.x == 0) {
        int orv = 0;
#pragma unroll
        for (int i = 0; i < 64; i++) orv |= ei32[2 * i + 1];
        g_is64 = (orv == 0) ? 1 : 0;
    }
}

__global__ void k_zero_deg() {
    int i = blockIdx.x * blockDim.x + threadIdx.x;
    if (i < N_NODES) g_deg[i] = 0;
}

__global__ void k_hist(const void* __restrict__ ei) {
    int e = blockIdx.x * blockDim.x + threadIdx.x;
    if (e >= N_EDGES) return;
    int dst = g_is64 ? (int)((const long long*)ei)[N_EDGES + e]
                     : ((const int*)ei)[N_EDGES + e];
    atomicAdd(&g_deg[dst], 1);
}

// ---------------- parallel 3-phase scan ----------------
__global__ void k_scan1() {
    __shared__ int sh[SCAN_BLK];
    int i = blockIdx.x * SCAN_BLK + threadIdx.x;
    int v = (i < N_NODES) ? g_deg[i] : 0;
    sh[threadIdx.x] = v;
    __syncthreads();
    for (int off = SCAN_BLK / 2; off > 0; off >>= 1) {
        if (threadIdx.x < off) sh[threadIdx.x] += sh[threadIdx.x + off];
        __syncthreads();
    }
    if (threadIdx.x == 0) g_bsum[blockIdx.x] = sh[0];
}

__global__ void k_scan2() {
    __shared__ int sh[SCAN_BLK];
    int t = threadIdx.x;
    int v = (t < NBLK) ? g_bsum[t] : 0;
    sh[t] = v;
    __syncthreads();
    for (int off = 1; off < SCAN_BLK; off <<= 1) {
        int add = (t >= off) ? sh[t - off] : 0;
        __syncthreads();
        sh[t] += add;
        __syncthreads();
    }
    if (t < NBLK) g_bsum[t] = sh[t] - v;          // exclusive
    if (t == 0) g_off[N_NODES] = N_EDGES;
}

__global__ void k_scan3() {
    __shared__ int sh[SCAN_BLK];
    int t = threadIdx.x;
    int i = blockIdx.x * SCAN_BLK + t;
    int v = (i < N_NODES) ? g_deg[i] : 0;
    sh[t] = v;
    __syncthreads();
    for (int off = 1; off < SCAN_BLK; off <<= 1) {
        int add = (t >= off) ? sh[t - off] : 0;
        __syncthreads();
        sh[t] += add;
        __syncthreads();
    }
    if (i < N_NODES) {
        int o = g_bsum[blockIdx.x] + sh[t] - v;    // exclusive global offset
        g_off[i] = o;
        g_cursor[i] = o;
    }
}

__global__ void k_scatter(const void* __restrict__ ei) {
    int e = blockIdx.x * blockDim.x + threadIdx.x;
    if (e >= N_EDGES) return;
    int src, dst;
    if (g_is64) {
        src = (int)((const long long*)ei)[e];
        dst = (int)((const long long*)ei)[N_EDGES + e];
    } else {
        src = ((const int*)ei)[e];
        dst = ((const int*)ei)[N_EDGES + e];
    }
    int pos = atomicAdd(&g_cursor[dst], 1);
    g_csr[pos] = src;
}

// ---------------- f32x2 helpers ----------------
__device__ __forceinline__ void fma2(ull& d, ull a, ull b) {
    asm("fma.rn.f32x2 %0, %1, %2, %0;" : "+l"(d) : "l"(a), "l"(b));
}
__device__ __forceinline__ ull dup2(float x) {
    ull r;
    asm("mov.b64 %0, {%1, %1};" : "=l"(r) : "f"(x));
    return r;
}
__device__ __forceinline__ void unpack2(ull v, float& lo, float& hi) {
    asm("mov.b64 {%0, %1}, %2;" : "=f"(lo), "=f"(hi) : "l"(v));
}

// ---------------- fused dual-output GEMM with f32x2 FMA ----------------
// out[n][h] = X[n][:] . Wcat[h][:] (+ bias on second half), h in [0, HOUT)
// Wcat row h = Wa[h] for h < H2, Wb[h-H2] for h >= H2.  K = 128.
// W stored transposed in smem: Wt[k][h], stride S, so adjacent-h pairs load
// pre-packed via LDS.64 (f32x2 operand). A scalar is dup-packed (mov.b64).
template <int HOUT>
__global__ void __launch_bounds__(256, 1)
k_gemm(const float* __restrict__ X,
       const float* __restrict__ Wa, const float* __restrict__ Wb,
       const float* __restrict__ bias, float* __restrict__ out) {
    constexpr int H2 = HOUT / 2;
    constexpr int J2 = HOUT / 32;          // f32x2 pairs per thread
    constexpr int S  = HOUT + 8;           // Wt float stride per k-row
    extern __shared__ float smf[];
    float*  Wt  = smf;                     // [128][S]
    float4* As4 = (float4*)(smf + 128 * S);  // [64][33]
    const int tid = threadIdx.x;

    // stage transposed concatenated weights once
    for (int idx = tid; idx < H2 * 128; idx += 256) {
        int h = idx >> 7, k = idx & 127;
        Wt[k * S + h]      = Wa[idx];
        Wt[k * S + H2 + h] = Wb[idx];
    }
    __syncthreads();

    const int tx = tid & 15, ty = tid >> 4;
    const int NT = (N_NODES + 63) >> 6;

    for (int tile = blockIdx.x; tile < NT; tile += gridDim.x) {
        const int n0 = tile << 6;
        // stage A tile: 64 nodes x 32 float4
        for (int idx = tid; idx < 64 * 32; idx += 256) {
            int r = idx >> 5, kq = idx & 31;
            int n = n0 + r;
            As4[r * 33 + kq] = (n < N_NODES)
                ? ((const float4*)X)[n * 32 + kq]
                : make_float4(0.f, 0.f, 0.f, 0.f);
        }
        __syncthreads();

        ull acc[4][J2];
#pragma unroll
        for (int i = 0; i < 4; i++)
#pragma unroll
            for (int j = 0; j < J2; j++) acc[i][j] = 0ull;

        const float4* Ar = As4 + (ty * 4) * 33;
#pragma unroll 2
        for (int kq = 0; kq < 32; kq++) {
            float4 a0 = Ar[kq];
            float4 a1 = Ar[33 + kq];
            float4 a2 = Ar[66 + kq];
            float4 a3 = Ar[99 + kq];
            ull aa[4][4];
            aa[0][0] = dup2(a0.x); aa[0][1] = dup2(a0.y); aa[0][2] = dup2(a0.z); aa[0][3] = dup2(a0.w);
            aa[1][0] = dup2(a1.x); aa[1][1] = dup2(a1.y); aa[1][2] = dup2(a1.z); aa[1][3] = dup2(a1.w);
            aa[2][0] = dup2(a2.x); aa[2][1] = dup2(a2.y); aa[2][2] = dup2(a2.z); aa[2][3] = dup2(a2.w);
            aa[3][0] = dup2(a3.x); aa[3][1] = dup2(a3.y); aa[3][2] = dup2(a3.z); aa[3][3] = dup2(a3.w);
#pragma unroll
            for (int c = 0; c < 4; c++) {
                const float* wrow = &Wt[(kq * 4 + c) * S];
#pragma unroll
                for (int j = 0; j < J2; j++) {
                    ull w2 = *(const ull*)&wrow[tx * 2 + j * 32];
                    fma2(acc[0][j], aa[0][c], w2);
                    fma2(acc[1][j], aa[1][c], w2);
                    fma2(acc[2][j], aa[2][c], w2);
                    fma2(acc[3][j], aa[3][c], w2);
                }
            }
        }

#pragma unroll
        for (int i = 0; i < 4; i++) {
            int n = n0 + ty * 4 + i;
            if (n < N_NODES) {
#pragma unroll
                for (int j = 0; j < J2; j++) {
                    int h0 = tx * 2 + j * 32;
                    float lo, hi;
                    unpack2(acc[i][j], lo, hi);
                    if (j >= J2 / 2) {                  // root half gets bias
                        lo += __ldg(&bias[h0 - H2]);
                        hi += __ldg(&bias[h0 - H2 + 1]);
                    }
                    *(float2*)&out[n * HOUT + h0] = make_float2(lo, hi);
                }
            }
        }
        __syncthreads();
    }
}

// ---------------- aggregation: t1[n] = relu( sum_{src} v[src] + s[n] ) ----------------
// vs1 rows: [v(32 float4) | s(32 float4)].  warp per node, float4 lanes.
__global__ void k_agg1(const float4* __restrict__ vs, float4* __restrict__ t1) {
    int gw = (blockIdx.x * blockDim.x + threadIdx.x) >> 5;
    int lane = threadIdx.x & 31;
    if (gw >= N_NODES) return;
    int beg = g_off[gw], end = g_off[gw + 1];
    float4 acc = vs[gw * 64 + 32 + lane];          // s row
    int j = beg;
    for (; j + 4 <= end; j += 4) {
        int s0 = g_csr[j], s1 = g_csr[j + 1], s2 = g_csr[j + 2], s3 = g_csr[j + 3];
        float4 a = vs[s0 * 64 + lane];
        float4 b = vs[s1 * 64 + lane];
        float4 c = vs[s2 * 64 + lane];
        float4 d = vs[s3 * 64 + lane];
        acc.x += (a.x + b.x) + (c.x + d.x);
        acc.y += (a.y + b.y) + (c.y + d.y);
        acc.z += (a.z + b.z) + (c.z + d.z);
        acc.w += (a.w + b.w) + (c.w + d.w);
    }
    for (; j < end; j++) {
        float4 a = vs[g_csr[j] * 64 + lane];
        acc.x += a.x; acc.y += a.y; acc.z += a.z; acc.w += a.w;
    }
    acc.x = fmaxf(acc.x, 0.f); acc.y = fmaxf(acc.y, 0.f);
    acc.z = fmaxf(acc.z, 0.f); acc.w = fmaxf(acc.w, 0.f);
    t1[gw * 32 + lane] = acc;
}

// ---------------- layer-2 aggregation: out[n] = sum u[src] + r[n]  (64-dim, float2 lanes)
__global__ void k_agg2(const float2* __restrict__ ur, float2* __restrict__ out) {
    int gw = (blockIdx.x * blockDim.x + threadIdx.x) >> 5;
    int lane = threadIdx.x & 31;
    if (gw >= N_NODES) return;
    int beg = g_off[gw], end = g_off[gw + 1];
    float2 acc = ur[gw * 64 + 32 + lane];          // r row
    int j = beg;
    for (; j + 4 <= end; j += 4) {
        int s0 = g_csr[j], s1 = g_csr[j + 1], s2 = g_csr[j + 2], s3 = g_csr[j + 3];
        float2 a = ur[s0 * 64 + lane];
        float2 b = ur[s1 * 64 + lane];
        float2 c = ur[s2 * 64 + lane];
        float2 d = ur[s3 * 64 + lane];
        acc.x += (a.x + b.x) + (c.x + d.x);
        acc.y += (a.y + b.y) + (c.y + d.y);
    }
    for (; j < end; j++) {
        float2 a = ur[g_csr[j] * 64 + lane];
        acc.x += a.x; acc.y += a.y;
    }
    out[gw * 32 + lane] = acc;
}

// ---------------- launch ----------------
extern "C" void kernel_launch(void* const* d_in, const int* in_sizes, int n_in,
                              void* d_out, int out_size) {
    const float* x      = (const float*)d_in[0];
    const void*  ei     = d_in[1];
    const float* Wrel1  = (const float*)d_in[2];
    const float* Wroot1 = (const float*)d_in[3];
    const float* b1     = (const float*)d_in[4];
    const float* Wrel2  = (const float*)d_in[5];
    const float* Wroot2 = (const float*)d_in[6];
    const float* b2     = (const float*)d_in[7];
    float* out = (float*)d_out;

    void *p_vs1 = nullptr, *p_t1 = nullptr, *p_vs2 = nullptr;
    cudaGetSymbolAddress(&p_vs1, g_vs1);
    cudaGetSymbolAddress(&p_t1, g_t1);
    cudaGetSymbolAddress(&p_vs2, g_vs2);

    const int SM1 = (128 * (256 + 8)) * 4 + 64 * 33 * 16;   // 168,960 B
    const int SM2 = (128 * (128 + 8)) * 4 + 64 * 33 * 16;   // 103,424 B
    cudaFuncSetAttribute(k_gemm<256>, cudaFuncAttributeMaxDynamicSharedMemorySize, SM1);
    cudaFuncSetAttribute(k_gemm<128>, cudaFuncAttributeMaxDynamicSharedMemorySize, SM2);

    // CSR build (parallel scan)
    k_detect<<<1, 32>>>((const int*)ei);
    k_zero_deg<<<(N_NODES + 255) / 256, 256>>>();
    k_hist<<<(N_EDGES + 255) / 256, 256>>>(ei);
    k_scan1<<<NBLK, SCAN_BLK>>>();
    k_scan2<<<1, SCAN_BLK>>>();
    k_scan3<<<NBLK, SCAN_BLK>>>();
    k_scatter<<<(N_EDGES + 255) / 256, 256>>>(ei);

    // layer 1: GEMM x -> [v|s], then gather-aggregate + relu
    k_gemm<256><<<148, 256, SM1>>>(x, Wrel1, Wroot1, b1, (float*)p_vs1);
    k_agg1<<<(N_NODES * 32 + 255) / 256, 256>>>((const float4*)p_vs1, (float4*)p_t1);

    // layer 2: GEMM t1 -> [u|r], then gather-aggregate
    k_gemm<128><<<148, 256, SM2>>>((const float*)p_t1, Wrel2, Wroot2, b2, (float*)p_vs2);
    k_agg2<<<(N_NODES * 32 + 255) / 256, 256>>>((const float2*)p_vs2, (float2*)d_out);
}

// round 3
// speedup vs baseline: 1.7531x; 1.0877x over previous
#include <cuda_runtime.h>
#include <cstdint>

#define N_NODES 50000
#define N_EDGES 800000
#define D_IN 128
#define H_DIM 128
#define D_OUT 64

#define SCAN_BLK 256
#define NBLK ((N_NODES + SCAN_BLK - 1) / SCAN_BLK)   // 196

typedef unsigned long long ull;

// ---------------- device scratch (static, no allocation) ----------------
__device__ float g_vs1[N_NODES * 256];   // layer1 GEMM out: [v(128) | s(128)] per node
__device__ float g_t1 [N_NODES * 128];   // layer1 activations
__device__ float g_vs2[N_NODES * 128];   // layer2 GEMM out: [u(64) | r(64)] per node
__device__ int   g_deg[N_NODES];
__device__ int   g_off[N_NODES + 1];
__device__ int   g_cursor[N_NODES];
__device__ int   g_csr[N_EDGES];
__device__ int   g_bsum[NBLK];
__device__ int   g_is64;

// ---------------- zero degrees + int64/int32 detection (fused) ----------------
__global__ void k_zero_detect(const int* __restrict__ ei32) {
    int i = blockIdx.x * blockDim.x + threadIdx.x;
    if (i < N_NODES) g_deg[i] = 0;
    if (i == 0) {
        int orv = 0;
#pragma unroll
        for (int k = 0; k < 64; k++) orv |= ei32[2 * k + 1];
        g_is64 = (orv == 0) ? 1 : 0;
    }
}

__global__ void k_hist(const void* __restrict__ ei) {
    int e = blockIdx.x * blockDim.x + threadIdx.x;
    if (e >= N_EDGES) return;
    int dst = g_is64 ? (int)((const long long*)ei)[N_EDGES + e]
                     : ((const int*)ei)[N_EDGES + e];
    atomicAdd(&g_deg[dst], 1);
}

// ---------------- parallel 3-phase scan ----------------
__global__ void k_scan1() {
    __shared__ int sh[SCAN_BLK];
    int i = blockIdx.x * SCAN_BLK + threadIdx.x;
    int v = (i < N_NODES) ? g_deg[i] : 0;
    sh[threadIdx.x] = v;
    __syncthreads();
    for (int off = SCAN_BLK / 2; off > 0; off >>= 1) {
        if (threadIdx.x < off) sh[threadIdx.x] += sh[threadIdx.x + off];
        __syncthreads();
    }
    if (threadIdx.x == 0) g_bsum[blockIdx.x] = sh[0];
}

__global__ void k_scan2() {
    __shared__ int sh[SCAN_BLK];
    int t = threadIdx.x;
    int v = (t < NBLK) ? g_bsum[t] : 0;
    sh[t] = v;
    __syncthreads();
    for (int off = 1; off < SCAN_BLK; off <<= 1) {
        int add = (t >= off) ? sh[t - off] : 0;
        __syncthreads();
        sh[t] += add;
        __syncthreads();
    }
    if (t < NBLK) g_bsum[t] = sh[t] - v;          // exclusive
    if (t == 0) g_off[N_NODES] = N_EDGES;
}

__global__ void k_scan3() {
    __shared__ int sh[SCAN_BLK];
    int t = threadIdx.x;
    int i = blockIdx.x * SCAN_BLK + t;
    int v = (i < N_NODES) ? g_deg[i] : 0;
    sh[t] = v;
    __syncthreads();
    for (int off = 1; off < SCAN_BLK; off <<= 1) {
        int add = (t >= off) ? sh[t - off] : 0;
        __syncthreads();
        sh[t] += add;
        __syncthreads();
    }
    if (i < N_NODES) {
        int o = g_bsum[blockIdx.x] + sh[t] - v;    // exclusive global offset
        g_off[i] = o;
        g_cursor[i] = o;
    }
}

__global__ void k_scatter(const void* __restrict__ ei) {
    int e = blockIdx.x * blockDim.x + threadIdx.x;
    if (e >= N_EDGES) return;
    int src, dst;
    if (g_is64) {
        src = (int)((const long long*)ei)[e];
        dst = (int)((const long long*)ei)[N_EDGES + e];
    } else {
        src = ((const int*)ei)[e];
        dst = ((const int*)ei)[N_EDGES + e];
    }
    int pos = atomicAdd(&g_cursor[dst], 1);
    g_csr[pos] = src;
}

// ---------------- f32x2 helpers ----------------
__device__ __forceinline__ void fma2(ull& d, ull a, ull b) {
    asm("fma.rn.f32x2 %0, %1, %2, %0;" : "+l"(d) : "l"(a), "l"(b));
}
__device__ __forceinline__ ull dup2(float x) {
    ull r;
    asm("mov.b64 %0, {%1, %1};" : "=l"(r) : "f"(x));
    return r;
}
__device__ __forceinline__ void unpack2(ull v, float& lo, float& hi) {
    asm("mov.b64 {%0, %1}, %2;" : "=f"(lo), "=f"(hi) : "l"(v));
}

// ---------------- fused dual-output GEMM with f32x2 FMA ----------------
// out[n][h] = X[n][:] . Wcat[h][:] (+ bias on second half), h in [0, HOUT)
// Wcat row h = Wa[h] for h < H2, Wb[h-H2] for h >= H2.  K = 128.
template <int HOUT>
__global__ void __launch_bounds__(256, 1)
k_gemm(const float* __restrict__ X,
       const float* __restrict__ Wa, const float* __restrict__ Wb,
       const float* __restrict__ bias, float* __restrict__ out) {
    constexpr int H2 = HOUT / 2;
    constexpr int J2 = HOUT / 32;          // f32x2 pairs per thread
    constexpr int S  = HOUT + 8;           // Wt float stride per k-row
    extern __shared__ float smf[];
    float*  Wt  = smf;                     // [128][S]
    float4* As4 = (float4*)(smf + 128 * S);  // [64][33]
    const int tid = threadIdx.x;

    for (int idx = tid; idx < H2 * 128; idx += 256) {
        int h = idx >> 7, k = idx & 127;
        Wt[k * S + h]      = Wa[idx];
        Wt[k * S + H2 + h] = Wb[idx];
    }
    __syncthreads();

    const int tx = tid & 15, ty = tid >> 4;
    const int NT = (N_NODES + 63) >> 6;

    for (int tile = blockIdx.x; tile < NT; tile += gridDim.x) {
        const int n0 = tile << 6;
        for (int idx = tid; idx < 64 * 32; idx += 256) {
            int r = idx >> 5, kq = idx & 31;
            int n = n0 + r;
            As4[r * 33 + kq] = (n < N_NODES)
                ? ((const float4*)X)[n * 32 + kq]
                : make_float4(0.f, 0.f, 0.f, 0.f);
        }
        __syncthreads();

        ull acc[4][J2];
#pragma unroll
        for (int i = 0; i < 4; i++)
#pragma unroll
            for (int j = 0; j < J2; j++) acc[i][j] = 0ull;

        const float4* Ar = As4 + (ty * 4) * 33;
#pragma unroll 2
        for (int kq = 0; kq < 32; kq++) {
            float4 a0 = Ar[kq];
            float4 a1 = Ar[33 + kq];
            float4 a2 = Ar[66 + kq];
            float4 a3 = Ar[99 + kq];
            ull aa[4][4];
            aa[0][0] = dup2(a0.x); aa[0][1] = dup2(a0.y); aa[0][2] = dup2(a0.z); aa[0][3] = dup2(a0.w);
            aa[1][0] = dup2(a1.x); aa[1][1] = dup2(a1.y); aa[1][2] = dup2(a1.z); aa[1][3] = dup2(a1.w);
            aa[2][0] = dup2(a2.x); aa[2][1] = dup2(a2.y); aa[2][2] = dup2(a2.z); aa[2][3] = dup2(a2.w);
            aa[3][0] = dup2(a3.x); aa[3][1] = dup2(a3.y); aa[3][2] = dup2(a3.z); aa[3][3] = dup2(a3.w);
#pragma unroll
            for (int c = 0; c < 4; c++) {
                const float* wrow = &Wt[(kq * 4 + c) * S];
#pragma unroll
                for (int j = 0; j < J2; j++) {
                    ull w2 = *(const ull*)&wrow[tx * 2 + j * 32];
                    fma2(acc[0][j], aa[0][c], w2);
                    fma2(acc[1][j], aa[1][c], w2);
                    fma2(acc[2][j], aa[2][c], w2);
                    fma2(acc[3][j], aa[3][c], w2);
                }
            }
        }

#pragma unroll
        for (int i = 0; i < 4; i++) {
            int n = n0 + ty * 4 + i;
            if (n < N_NODES) {
#pragma unroll
                for (int j = 0; j < J2; j++) {
                    int h0 = tx * 2 + j * 32;
                    float lo, hi;
                    unpack2(acc[i][j], lo, hi);
                    if (j >= J2 / 2) {                  // root half gets bias
                        lo += __ldg(&bias[h0 - H2]);
                        hi += __ldg(&bias[h0 - H2 + 1]);
                    }
                    *(float2*)&out[n * HOUT + h0] = make_float2(lo, hi);
                }
            }
        }
        __syncthreads();
    }
}

// ---------------- aggregation: t1[n] = relu( sum_{src} v[src] + s[n] ) ----------------
__global__ void k_agg1(const float4* __restrict__ vs, float4* __restrict__ t1) {
    int gw = (blockIdx.x * blockDim.x + threadIdx.x) >> 5;
    int lane = threadIdx.x & 31;
    if (gw >= N_NODES) return;
    int beg = g_off[gw], end = g_off[gw + 1];
    float4 acc = vs[gw * 64 + 32 + lane];          // s row
    int j = beg;
    for (; j + 4 <= end; j += 4) {
        int s0 = g_csr[j], s1 = g_csr[j + 1], s2 = g_csr[j + 2], s3 = g_csr[j + 3];
        float4 a = vs[s0 * 64 + lane];
        float4 b = vs[s1 * 64 + lane];
        float4 c = vs[s2 * 64 + lane];
        float4 d = vs[s3 * 64 + lane];
        acc.x += (a.x + b.x) + (c.x + d.x);
        acc.y += (a.y + b.y) + (c.y + d.y);
        acc.z += (a.z + b.z) + (c.z + d.z);
        acc.w += (a.w + b.w) + (c.w + d.w);
    }
    for (; j < end; j++) {
        float4 a = vs[g_csr[j] * 64 + lane];
        acc.x += a.x; acc.y += a.y; acc.z += a.z; acc.w += a.w;
    }
    acc.x = fmaxf(acc.x, 0.f); acc.y = fmaxf(acc.y, 0.f);
    acc.z = fmaxf(acc.z, 0.f); acc.w = fmaxf(acc.w, 0.f);
    t1[gw * 32 + lane] = acc;
}

// ---------------- layer-2 aggregation: out[n] = sum u[src] + r[n]  (64-dim) ----------------
__global__ void k_agg2(const float2* __restrict__ ur, float2* __restrict__ out) {
    int gw = (blockIdx.x * blockDim.x + threadIdx.x) >> 5;
    int lane = threadIdx.x & 31;
    if (gw >= N_NODES) return;
    int beg = g_off[gw], end = g_off[gw + 1];
    float2 acc = ur[gw * 64 + 32 + lane];          // r row
    int j = beg;
    for (; j + 4 <= end; j += 4) {
        int s0 = g_csr[j], s1 = g_csr[j + 1], s2 = g_csr[j + 2], s3 = g_csr[j + 3];
        float2 a = ur[s0 * 64 + lane];
        float2 b = ur[s1 * 64 + lane];
        float2 c = ur[s2 * 64 + lane];
        float2 d = ur[s3 * 64 + lane];
        acc.x += (a.x + b.x) + (c.x + d.x);
        acc.y += (a.y + b.y) + (c.y + d.y);
    }
    for (; j < end; j++) {
        float2 a = ur[g_csr[j] * 64 + lane];
        acc.x += a.x; acc.y += a.y;
    }
    out[gw * 32 + lane] = acc;
}

// ---------------- launch: CSR chain forked onto a side stream ----------------
extern "C" void kernel_launch(void* const* d_in, const int* in_sizes, int n_in,
                              void* d_out, int out_size) {
    const float* x      = (const float*)d_in[0];
    const void*  ei     = d_in[1];
    const float* Wrel1  = (const float*)d_in[2];
    const float* Wroot1 = (const float*)d_in[3];
    const float* b1     = (const float*)d_in[4];
    const float* Wrel2  = (const float*)d_in[5];
    const float* Wroot2 = (const float*)d_in[6];
    const float* b2     = (const float*)d_in[7];

    void *p_vs1 = nullptr, *p_t1 = nullptr, *p_vs2 = nullptr;
    cudaGetSymbolAddress(&p_vs1, g_vs1);
    cudaGetSymbolAddress(&p_t1, g_t1);
    cudaGetSymbolAddress(&p_vs2, g_vs2);

    const int SM1 = (128 * (256 + 8)) * 4 + 64 * 33 * 16;   // 168,960 B
    const int SM2 = (128 * (128 + 8)) * 4 + 64 * 33 * 16;   // 103,424 B
    cudaFuncSetAttribute(k_gemm<256>, cudaFuncAttributeMaxDynamicSharedMemorySize, SM1);
    cudaFuncSetAttribute(k_gemm<128>, cudaFuncAttributeMaxDynamicSharedMemorySize, SM2);

    // lazily-created side stream + fork/join events (created outside capture on
    // the first correctness call; reused identically on the capture call)
    static cudaStream_t s1 = nullptr;
    static cudaEvent_t evRoot = nullptr, evCsr = nullptr;
    if (s1 == nullptr) {
        cudaStreamCreateWithFlags(&s1, cudaStreamNonBlocking);
        cudaEventCreateWithFlags(&evRoot, cudaEventDisableTiming);
        cudaEventCreateWithFlags(&evCsr, cudaEventDisableTiming);
    }

    // fork: CSR build on s1, concurrent with layer-1 GEMM on stream 0
    cudaEventRecord(evRoot, 0);
    cudaStreamWaitEvent(s1, evRoot, 0);
    k_zero_detect<<<(N_NODES + 255) / 256, 256, 0, s1>>>((const int*)ei);
    k_hist<<<(N_EDGES + 255) / 256, 256, 0, s1>>>(ei);
    k_scan1<<<NBLK, SCAN_BLK, 0, s1>>>();
    k_scan2<<<1, SCAN_BLK, 0, s1>>>();
    k_scan3<<<NBLK, SCAN_BLK, 0, s1>>>();
    k_scatter<<<(N_EDGES + 255) / 256, 256, 0, s1>>>(ei);
    cudaEventRecord(evCsr, s1);

    // layer-1 GEMM x -> [v|s] (independent of CSR)
    k_gemm<256><<<148, 256, SM1>>>(x, Wrel1, Wroot1, b1, (float*)p_vs1);

    // join: aggregation needs both GEMM1 output and the CSR
    cudaStreamWaitEvent(0, evCsr, 0);
    k_agg1<<<(N_NODES * 32 + 255) / 256, 256>>>((const float4*)p_vs1, (float4*)p_t1);

    // layer 2
    k_gemm<128><<<148, 256, SM2>>>((const float*)p_t1, Wrel2, Wroot2, b2, (float*)p_vs2);
    k_agg2<<<(N_NODES * 32 + 255) / 256, 256>>>((const float2*)p_vs2, (float2*)d_out);
}